// round 2
// baseline (speedup 1.0000x reference)
#include <cuda_runtime.h>

#define DIM 128
#define LMAX 20

__global__ void sg_init_out(float* out) { out[0] = 0.0f; }

__global__ void __launch_bounds__(256) sg_loss_kernel(
    const float* __restrict__ W0,
    const float* __restrict__ W1,
    const int* __restrict__ target,
    const int* __restrict__ context,
    const int* __restrict__ codes,
    const int* __restrict__ lengths,
    float* __restrict__ out,
    int B,
    int n_nodes)
{
    const int gwarp = (blockIdx.x * blockDim.x + threadIdx.x) >> 5;
    const int lane  = threadIdx.x & 31;
    const int wid   = threadIdx.x >> 5;

    float partial = 0.0f;

    if (gwarp < B) {
        const int t = target[gwarp];
        const int c = context[gwarp];

        // Bounds guard: if index dtype assumption is wrong, finish with wrong
        // answer (diagnostic rel_err) instead of an illegal access.
        if (t >= 0 && t < n_nodes && c >= 0 && c < n_nodes) {
            // 512B row gather per table: one float4 per lane, coalesced.
            const float4 a = reinterpret_cast<const float4*>(W0 + (long long)t * DIM)[lane];
            const float4 b = reinterpret_cast<const float4*>(W1 + (long long)c * DIM)[lane];

            float dot = a.x * b.x + a.y * b.y + a.z * b.z + a.w * b.w;
            #pragma unroll
            for (int o = 16; o > 0; o >>= 1)
                dot += __shfl_xor_sync(0xffffffffu, dot, o);
            // all lanes now hold the full dot

            // lanes 0..19 each evaluate one tree level (coalesced codes read)
            float acc = 0.0f;
            if (lane < LMAX) {
                const int len = lengths[gwarp];           // broadcast load
                if (lane < len) {
                    const int code = codes[gwarp * LMAX + lane];
                    const float sign = 1.0f - 2.0f * (float)code;
                    const float x = sign * dot;
                    // stable log_sigmoid: min(x,0) - log1p(exp(-|x|))
                    const float ls = fminf(x, 0.0f) - log1pf(__expf(-fabsf(x)));
                    acc = -ls;
                }
            }
            #pragma unroll
            for (int o = 16; o > 0; o >>= 1)
                acc += __shfl_xor_sync(0xffffffffu, acc, o);
            partial = acc;
        }
    }

    // block reduce: one partial per warp
    __shared__ float smem[8];
    if (lane == 0) smem[wid] = partial;
    __syncthreads();
    if (threadIdx.x == 0) {
        float s = 0.0f;
        #pragma unroll
        for (int i = 0; i < 8; ++i) s += smem[i];
        atomicAdd(out, s);
    }
}

extern "C" void kernel_launch(void* const* d_in, const int* in_sizes, int n_in,
                              void* d_out, int out_size)
{
    const float* W0      = (const float*)d_in[0];
    const float* W1      = (const float*)d_in[1];
    const int*   target  = (const int*)d_in[2];
    const int*   context = (const int*)d_in[3];
    const int*   codes   = (const int*)d_in[4];
    const int*   lengths = (const int*)d_in[5];
    float* out = (float*)d_out;

    const int B = in_sizes[2];                 // 16384
    const int n_nodes = in_sizes[0] / DIM;     // 1,000,000
    sg_init_out<<<1, 1>>>(out);
    const int warps_per_block = 256 / 32;      // 8
    const int blocks = (B + warps_per_block - 1) / warps_per_block;  // 2048
    sg_loss_kernel<<<blocks, 256>>>(W0, W1, target, context, codes, lengths, out, B, n_nodes);
}